// round 1
// baseline (speedup 1.0000x reference)
#include <cuda_runtime.h>

#define Bn 8192
#define Dn 2048
#define Cn 751
#define NCAMS 16
#define MARGINF 0.3f
#define INV_TEMP (1.0f/0.07f)
#define BIGF 1.0e9f
#define L_TRI 0.5f
#define L_ST 0.3f

#define BM 128
#define BNN 128
#define BK 16
#define LDP 132            // padded smem leading dim (bank-friendly, float4-aligned)
#define NSPLIT 4
#define COLS_PER (Bn/NSPLIT)
#define CT_PER (COLS_PER/BNN)
#define KT (Dn/BK)

// ---------------- scratch (device globals: no allocation allowed) ----------------
__device__ float    g_sq[Bn], g_invn[Bn];
__device__ float    g_sume[Bn], g_spos[Bn], g_cpos[Bn];
__device__ unsigned g_hp[Bn], g_hn[Bn];
__device__ float    g_sume_cls[Bn], g_lab_logit[Bn];
__device__ float    g_acc[8];   // 0 tri_sum, 1 n_valid, 2 st_num, 3 st_den(n_pos), 4 cls_sum

// monotone float<->uint encoding so atomicMax/Min work on floats (incl. negatives)
__device__ __forceinline__ unsigned f2o(float f){
    unsigned u = __float_as_uint(f);
    return (u & 0x80000000u) ? ~u : (u | 0x80000000u);
}
__device__ __forceinline__ float o2f(unsigned u){
    return __uint_as_float((u & 0x80000000u) ? (u & 0x7fffffffu) : ~u);
}

// ---------------- init ----------------
__global__ void init_kernel(){
    int i = blockIdx.x*blockDim.x + threadIdx.x;
    if (i < Bn){
        g_sume[i]=0.f; g_spos[i]=0.f; g_cpos[i]=0.f;
        g_hp[i]=f2o(-BIGF); g_hn[i]=f2o(BIGF);
        g_sume_cls[i]=0.f; g_lab_logit[i]=0.f;
    }
    if (i < 8) g_acc[i]=0.f;
}

// ---------------- row norms ----------------
__global__ void norm_kernel(const float* __restrict__ F){
    int row  = blockIdx.x*(blockDim.x>>5) + (threadIdx.x>>5);
    int lane = threadIdx.x & 31;
    const float4* p = (const float4*)(F + (size_t)row*Dn);
    float s = 0.f;
    #pragma unroll
    for (int i = lane; i < Dn/4; i += 32){
        float4 v = p[i];
        s += v.x*v.x + v.y*v.y + v.z*v.z + v.w*v.w;
    }
    #pragma unroll
    for (int o=16;o;o>>=1) s += __shfl_xor_sync(0xffffffffu, s, o);
    if (lane==0){ g_sq[row]=s; g_invn[row]=rsqrtf(s); }
}

#define STORE4(dst, bb, vv, idx) \
    do { dst[bb][kq+0][idx]=vv.x; dst[bb][kq+1][idx]=vv.y; \
         dst[bb][kq+2][idx]=vv.z; dst[bb][kq+3][idx]=vv.w; } while(0)

// ---------------- fused Gram-matrix kernel: triplet + ST-contrastive stats ----------------
__global__ __launch_bounds__(256) void pair_kernel(
    const float* __restrict__ F, const int* __restrict__ lab,
    const int* __restrict__ cam, const float* __restrict__ ts,
    const float* __restrict__ reach)
{
    __shared__ float As[2][BK][LDP];
    __shared__ float Bs[2][BK][LDP];
    __shared__ float s_reach[NCAMS*NCAMS];
    int tid = threadIdx.x;
    s_reach[tid] = reach[tid];             // 256 threads == 256 entries

    int row0 = blockIdx.x * BM;
    int tx = tid & 15, ty = tid >> 4;
    int tm0 = ty*8, tn0 = tx*8;
    int lm = tid >> 2;                     // 0..63
    int kq = (tid & 3) * 4;                // 0,4,8,12

    // anchor-row metadata (fixed for whole CTA)
    float sqi[8], invni[8], tsi[8]; int labi[8], cami[8];
    #pragma unroll
    for (int r=0;r<8;r++){
        int ri = row0 + tm0 + r;
        sqi[r]=g_sq[ri]; invni[r]=g_invn[ri]; tsi[r]=ts[ri];
        labi[r]=lab[ri]; cami[r]=cam[ri]*NCAMS;
    }
    // per-row running stats (merged across grid at the end)
    float sume[8], spos[8], cpos[8], hp[8], hn[8];
    #pragma unroll
    for (int r=0;r<8;r++){ sume[r]=0.f; spos[r]=0.f; cpos[r]=0.f; hp[r]=-BIGF; hn[r]=BIGF; }
    __syncthreads();

    const float* Arow0 = F + (size_t)(row0+lm   )*Dn + kq;
    const float* Arow1 = F + (size_t)(row0+lm+64)*Dn + kq;

    for (int ct=0; ct<CT_PER; ct++){
        int col0 = blockIdx.y*COLS_PER + ct*BNN;
        const float* Brow0 = F + (size_t)(col0+lm   )*Dn + kq;
        const float* Brow1 = F + (size_t)(col0+lm+64)*Dn + kq;

        float acc[8][8];
        #pragma unroll
        for (int i=0;i<8;i++)
            #pragma unroll
            for (int j=0;j<8;j++) acc[i][j]=0.f;

        { // preload tile 0
            float4 a0=*(const float4*)(Arow0);
            float4 a1=*(const float4*)(Arow1);
            float4 b0=*(const float4*)(Brow0);
            float4 b1=*(const float4*)(Brow1);
            STORE4(As,0,a0,lm); STORE4(As,0,a1,lm+64);
            STORE4(Bs,0,b0,lm); STORE4(Bs,0,b1,lm+64);
        }
        __syncthreads();

        int buf = 0;
        for (int kt=0; kt<KT; kt++){
            float4 a0,a1,b0,b1;
            bool pf = (kt+1 < KT);
            if (pf){
                int k0 = (kt+1)*BK;
                a0=*(const float4*)(Arow0+k0);
                a1=*(const float4*)(Arow1+k0);
                b0=*(const float4*)(Brow0+k0);
                b1=*(const float4*)(Brow1+k0);
            }
            #pragma unroll
            for (int kk=0; kk<BK; kk++){
                float av[8], bv[8];
                *(float4*)&av[0]=*(const float4*)&As[buf][kk][tm0];
                *(float4*)&av[4]=*(const float4*)&As[buf][kk][tm0+4];
                *(float4*)&bv[0]=*(const float4*)&Bs[buf][kk][tn0];
                *(float4*)&bv[4]=*(const float4*)&Bs[buf][kk][tn0+4];
                #pragma unroll
                for (int i=0;i<8;i++)
                    #pragma unroll
                    for (int j=0;j<8;j++) acc[i][j] += av[i]*bv[j];
            }
            if (pf){
                int nb = buf^1;
                STORE4(As,nb,a0,lm); STORE4(As,nb,a1,lm+64);
                STORE4(Bs,nb,b0,lm); STORE4(Bs,nb,b1,lm+64);
                __syncthreads();
                buf = nb;
            }
        }

        // ---- fused epilogue over this 128x128 G tile ----
        float sqj[8], invnj[8], tsj[8]; int labj[8], camj[8];
        #pragma unroll
        for (int c=0;c<8;c++){
            int cj = col0 + tn0 + c;
            sqj[c]=g_sq[cj]; invnj[c]=g_invn[cj]; tsj[c]=ts[cj];
            labj[c]=lab[cj]; camj[c]=cam[cj];
        }
        #pragma unroll
        for (int r=0;r<8;r++){
            int ri = row0 + tm0 + r;
            #pragma unroll
            for (int c=0;c<8;c++){
                int cj = col0 + tn0 + c;
                float g  = acc[r][c];
                float d2 = fmaxf(sqi[r] + sqj[c] - 2.f*g, 0.f);
                bool eye  = (ri == cj);
                bool same = (labi[r] == labj[c]);
                if (same && !eye) hp[r] = fmaxf(hp[r], d2);
                else              hn[r] = fminf(hn[r], d2);
                float sim = g * invni[r] * invnj[c] * INV_TEMP;
                sume[r] += __expf(sim - INV_TEMP);          // fixed shift M = 1/TEMP (sim <= M by C-S)
                float dt = fabsf(tsi[r] - tsj[c]);
                bool reach_ok = (dt <= s_reach[cami[r] + camj[c]]) && !eye;
                if (same && reach_ok){ spos[r] += sim; cpos[r] += 1.f; }
            }
        }
        __syncthreads();
    }

    // reduce across the 16 column-threads of each row group, then merge globally
    #pragma unroll
    for (int o=8;o;o>>=1){
        #pragma unroll
        for (int r=0;r<8;r++){
            sume[r] += __shfl_down_sync(0xffffffffu, sume[r], o, 16);
            spos[r] += __shfl_down_sync(0xffffffffu, spos[r], o, 16);
            cpos[r] += __shfl_down_sync(0xffffffffu, cpos[r], o, 16);
            hp[r] = fmaxf(hp[r], __shfl_down_sync(0xffffffffu, hp[r], o, 16));
            hn[r] = fminf(hn[r], __shfl_down_sync(0xffffffffu, hn[r], o, 16));
        }
    }
    if (tx == 0){
        #pragma unroll
        for (int r=0;r<8;r++){
            int ri = row0 + tm0 + r;
            atomicAdd(&g_sume[ri], sume[r]);
            atomicAdd(&g_spos[ri], spos[r]);
            atomicAdd(&g_cpos[ri], cpos[r]);
            atomicMax(&g_hp[ri], f2o(hp[r]));
            atomicMin(&g_hn[ri], f2o(hn[r]));
        }
    }
}

// ---------------- classifier: logits GEMM + fused sum-exp / label-logit ----------------
__global__ __launch_bounds__(256) void cls_kernel(
    const float* __restrict__ F, const float* __restrict__ W,
    const float* __restrict__ bb, const int* __restrict__ lab)
{
    __shared__ float As[2][BK][LDP];
    __shared__ float Bs[2][BK][LDP];
    int tid = threadIdx.x;
    int row0 = blockIdx.x * BM;
    int col0 = blockIdx.y * BNN;
    int tx = tid & 15, ty = tid >> 4;
    int tm0 = ty*8, tn0 = tx*8;
    int lm = tid >> 2; int kq = (tid & 3)*4;

    const float* Arow0 = F + (size_t)(row0+lm   )*Dn + kq;
    const float* Arow1 = F + (size_t)(row0+lm+64)*Dn + kq;
    int  wr0 = col0+lm, wr1 = col0+lm+64;
    bool v0 = wr0 < Cn, v1 = wr1 < Cn;
    const float* Brow0 = W + (size_t)(v0?wr0:0)*Dn + kq;
    const float* Brow1 = W + (size_t)(v1?wr1:0)*Dn + kq;
    const float4 ZF = make_float4(0.f,0.f,0.f,0.f);

    float acc[8][8];
    #pragma unroll
    for (int i=0;i<8;i++)
        #pragma unroll
        for (int j=0;j<8;j++) acc[i][j]=0.f;

    {
        float4 a0=*(const float4*)(Arow0);
        float4 a1=*(const float4*)(Arow1);
        float4 b0=*(const float4*)(Brow0); if(!v0) b0=ZF;
        float4 b1=*(const float4*)(Brow1); if(!v1) b1=ZF;
        STORE4(As,0,a0,lm); STORE4(As,0,a1,lm+64);
        STORE4(Bs,0,b0,lm); STORE4(Bs,0,b1,lm+64);
    }
    __syncthreads();

    int buf = 0;
    for (int kt=0; kt<KT; kt++){
        float4 a0,a1,b0,b1;
        bool pf = (kt+1 < KT);
        if (pf){
            int k0 = (kt+1)*BK;
            a0=*(const float4*)(Arow0+k0);
            a1=*(const float4*)(Arow1+k0);
            b0=*(const float4*)(Brow0+k0); if(!v0) b0=ZF;
            b1=*(const float4*)(Brow1+k0); if(!v1) b1=ZF;
        }
        #pragma unroll
        for (int kk=0; kk<BK; kk++){
            float av[8], bv[8];
            *(float4*)&av[0]=*(const float4*)&As[buf][kk][tm0];
            *(float4*)&av[4]=*(const float4*)&As[buf][kk][tm0+4];
            *(float4*)&bv[0]=*(const float4*)&Bs[buf][kk][tn0];
            *(float4*)&bv[4]=*(const float4*)&Bs[buf][kk][tn0+4];
            #pragma unroll
            for (int i=0;i<8;i++)
                #pragma unroll
                for (int j=0;j<8;j++) acc[i][j] += av[i]*bv[j];
        }
        if (pf){
            int nb = buf^1;
            STORE4(As,nb,a0,lm); STORE4(As,nb,a1,lm+64);
            STORE4(Bs,nb,b0,lm); STORE4(Bs,nb,b1,lm+64);
            __syncthreads();
            buf = nb;
        }
    }

    int labi[8];
    #pragma unroll
    for (int r=0;r<8;r++) labi[r]=lab[row0+tm0+r];
    float se[8];
    #pragma unroll
    for (int r=0;r<8;r++) se[r]=0.f;
    #pragma unroll
    for (int c=0;c<8;c++){
        int cj = col0 + tn0 + c;
        bool valid = cj < Cn;
        float bj = valid ? bb[cj] : 0.f;
        #pragma unroll
        for (int r=0;r<8;r++){
            float logit = acc[r][c] + bj;
            if (valid){
                se[r] += __expf(logit);                // logits ~ N(0,1): safe without max-shift
                if (cj == labi[r]) g_lab_logit[row0+tm0+r] = logit;
            }
        }
    }
    #pragma unroll
    for (int o=8;o;o>>=1)
        #pragma unroll
        for (int r=0;r<8;r++) se[r] += __shfl_down_sync(0xffffffffu, se[r], o, 16);
    if (tx == 0){
        #pragma unroll
        for (int r=0;r<8;r++) atomicAdd(&g_sume_cls[row0+tm0+r], se[r]);
    }
}

// ---------------- final reductions ----------------
__global__ void fin1(){
    int i = blockIdx.x*blockDim.x + threadIdx.x;
    float tri=0.f, nv=0.f, stn=0.f, stc=0.f, cls=0.f;
    if (i < Bn){
        float lse = INV_TEMP + logf(g_sume[i]);
        stn = g_spos[i] - g_cpos[i]*lse;
        stc = g_cpos[i];
        float hp = o2f(g_hp[i]), hn = o2f(g_hn[i]);
        bool valid = hp > -1.0e8f;                     // any positive existed
        tri = valid ? fmaxf(hp - hn + MARGINF, 0.f) : 0.f;
        nv  = valid ? 1.f : 0.f;
        cls = logf(g_sume_cls[i]) - g_lab_logit[i];
    }
    #pragma unroll
    for (int o=16;o;o>>=1){
        tri += __shfl_down_sync(0xffffffffu, tri, o);
        nv  += __shfl_down_sync(0xffffffffu, nv , o);
        stn += __shfl_down_sync(0xffffffffu, stn, o);
        stc += __shfl_down_sync(0xffffffffu, stc, o);
        cls += __shfl_down_sync(0xffffffffu, cls, o);
    }
    if ((threadIdx.x & 31) == 0){
        atomicAdd(&g_acc[0], tri);
        atomicAdd(&g_acc[1], nv);
        atomicAdd(&g_acc[2], stn);
        atomicAdd(&g_acc[3], stc);
        atomicAdd(&g_acc[4], cls);
    }
}

__global__ void fin2(float* out){
    float nv = g_acc[1], npos = g_acc[3];
    float loss_id  = g_acc[4] / (float)Bn;
    float loss_tri = (nv   > 0.f) ? g_acc[0] / fmaxf(nv,   1.f) : 0.f;
    float loss_st  = (npos > 0.f) ? (-g_acc[2]) / fmaxf(npos, 1.f) : 0.f;
    out[0] = loss_id + L_TRI*loss_tri + L_ST*loss_st;
}

// ---------------- launch ----------------
extern "C" void kernel_launch(void* const* d_in, const int* in_sizes, int n_in,
                              void* d_out, int out_size){
    const float* F     = (const float*)d_in[0];
    const int*   lab   = (const int*)  d_in[1];
    const int*   cam   = (const int*)  d_in[2];
    const float* ts    = (const float*)d_in[3];
    const float* reach = (const float*)d_in[4];
    const float* W     = (const float*)d_in[5];
    const float* bb    = (const float*)d_in[6];
    float* out = (float*)d_out;

    init_kernel<<<(Bn+255)/256, 256>>>();
    norm_kernel<<<Bn/8, 256>>>(F);
    dim3 g1(Bn/BM, NSPLIT);
    pair_kernel<<<g1, 256>>>(F, lab, cam, ts, reach);
    dim3 g2(Bn/BM, (Cn+BNN-1)/BNN);
    cls_kernel<<<g2, 256>>>(F, W, bb, lab);
    fin1<<<Bn/256, 256>>>();
    fin2<<<1,1>>>(out);
}

// round 2
// speedup vs baseline: 4.7741x; 4.7741x over previous
#include <cuda_runtime.h>
#include <cuda_bf16.h>
#include <cstdint>

#define Bn 8192
#define Dn 2048
#define Cn 751
#define CnP 768
#define NCAMS 16
#define MARGINF 0.3f
#define IT (1.0f/0.07f)
#define L2E 1.44269504f
#define LN2f 0.69314718f
#define CEXP (IT*L2E)
#define BIGF 1.0e9f
#define L_TRI 0.5f
#define L_ST 0.3f

#define BM 128
#define BN2 128
#define BKb 32
#define KT2 (Dn/BKb)           // 64
#define NSPLIT 4
#define COLS_PER (Bn/NSPLIT)   // 2048
#define CT_PER (COLS_PER/BN2)  // 16

// ---------------- device scratch (no allocation allowed) ----------------
__device__ __nv_bfloat16 g_Fb[(size_t)Bn*Dn];   // 32 MB
__device__ __nv_bfloat16 g_Wb[(size_t)CnP*Dn];  // 3 MB (rows >= Cn zeroed)
__device__ float    g_sq[Bn], g_invn[Bn];
__device__ float    g_sume[Bn], g_spos[Bn], g_cpos[Bn];
__device__ unsigned g_hp[Bn], g_hn[Bn];
__device__ float    g_sume_cls[Bn], g_lab_logit[Bn];
__device__ float    g_acc[8];

// monotone float<->uint for atomic max/min on floats
__device__ __forceinline__ unsigned f2o(float f){
    unsigned u = __float_as_uint(f);
    return (u & 0x80000000u) ? ~u : (u | 0x80000000u);
}
__device__ __forceinline__ float o2f(unsigned u){
    return __uint_as_float((u & 0x80000000u) ? (u & 0x7fffffffu) : ~u);
}

__device__ __forceinline__ uint32_t pack_bf(float a, float b){
    __nv_bfloat162 t = __floats2bfloat162_rn(a, b);
    return *reinterpret_cast<uint32_t*>(&t);
}
__device__ __forceinline__ float sq2(uint32_t u){
    __nv_bfloat162 h = *reinterpret_cast<__nv_bfloat162*>(&u);
    float2 f = __bfloat1622float2(h);
    return f.x*f.x + f.y*f.y;
}

__device__ __forceinline__ void ldm4(uint32_t &r0, uint32_t &r1, uint32_t &r2, uint32_t &r3, uint32_t addr){
    asm volatile("ldmatrix.sync.aligned.m8n8.x4.shared.b16 {%0,%1,%2,%3}, [%4];"
        : "=r"(r0), "=r"(r1), "=r"(r2), "=r"(r3) : "r"(addr));
}
__device__ __forceinline__ void mma16816(float* d, const uint32_t* a, const uint32_t* b){
    asm volatile("mma.sync.aligned.m16n8k16.row.col.f32.bf16.bf16.f32 "
        "{%0,%1,%2,%3}, {%4,%5,%6,%7}, {%8,%9}, {%0,%1,%2,%3};"
        : "+f"(d[0]), "+f"(d[1]), "+f"(d[2]), "+f"(d[3])
        : "r"(a[0]), "r"(a[1]), "r"(a[2]), "r"(a[3]), "r"(b[0]), "r"(b[1]));
}

// ---------------- conversion ----------------
__global__ void convert_F_kernel(const float* __restrict__ F){
    size_t i = ((size_t)blockIdx.x*blockDim.x + threadIdx.x)*8;
    float4 v0 = *(const float4*)(F+i);
    float4 v1 = *(const float4*)(F+i+4);
    uint4 o;
    o.x = pack_bf(v0.x, v0.y); o.y = pack_bf(v0.z, v0.w);
    o.z = pack_bf(v1.x, v1.y); o.w = pack_bf(v1.z, v1.w);
    *(uint4*)(g_Fb + i) = o;
}
__global__ void convert_W_kernel(const float* __restrict__ W){
    size_t i = ((size_t)blockIdx.x*blockDim.x + threadIdx.x)*8;
    size_t row = i / Dn;
    uint4 o;
    if (row < Cn){
        float4 v0 = *(const float4*)(W+i);
        float4 v1 = *(const float4*)(W+i+4);
        o.x = pack_bf(v0.x, v0.y); o.y = pack_bf(v0.z, v0.w);
        o.z = pack_bf(v1.x, v1.y); o.w = pack_bf(v1.z, v1.w);
    } else {
        o.x = o.y = o.z = o.w = 0u;
    }
    *(uint4*)(g_Wb + i) = o;
}

// ---------------- init ----------------
__global__ void init_kernel(){
    int i = blockIdx.x*blockDim.x + threadIdx.x;
    if (i < Bn){
        g_sume[i]=0.f; g_spos[i]=0.f; g_cpos[i]=0.f;
        g_hp[i]=f2o(-BIGF); g_hn[i]=f2o(BIGF);
        g_sume_cls[i]=0.f; g_lab_logit[i]=0.f;
    }
    if (i < 8) g_acc[i]=0.f;
}

// ---------------- row norms from bf16-rounded features ----------------
__global__ void norm_kernel(){
    int row  = blockIdx.x*(blockDim.x>>5) + (threadIdx.x>>5);
    int lane = threadIdx.x & 31;
    const uint4* p = (const uint4*)(g_Fb + (size_t)row*Dn);
    float s = 0.f;
    #pragma unroll
    for (int i = lane; i < Dn/8; i += 32){
        uint4 v = p[i];
        s += sq2(v.x) + sq2(v.y) + sq2(v.z) + sq2(v.w);
    }
    #pragma unroll
    for (int o=16;o;o>>=1) s += __shfl_xor_sync(0xffffffffu, s, o);
    if (lane==0){ g_sq[row]=s; g_invn[row]=rsqrtf(s); }
}

// swizzled smem offset: 64B rows, 16B chunks, perm = c ^ ((row>>1)&3)
#define SWOFF(row, c) ((row)*64 + ((((c) ^ (((row)>>1)&3)))<<4))

// ---------------- fused Gram kernel (tensor cores) ----------------
__global__ __launch_bounds__(256) void pair_kernel(
    const int* __restrict__ lab, const int* __restrict__ cam,
    const float* __restrict__ ts, const float* __restrict__ reach)
{
    __shared__ alignas(16) char As[2][8192];
    __shared__ alignas(16) char Bs[2][8192];
    __shared__ float s_sq[BN2], s_invn[BN2], s_ts[BN2];
    __shared__ int   s_lab[BN2], s_cam[BN2];
    __shared__ float s_reach[256];

    int tid = threadIdx.x, lane = tid&31, wid = tid>>5;
    s_reach[tid] = reach[tid];

    int row0 = blockIdx.x*BM;
    int wm = wid&3, wn = wid>>2;

    // global->smem loader mapping (each thread: 32B of A + 32B of B per k-step)
    int rowA = tid>>1;
    int cp   = (tid&1)*2;
    int offL0 = SWOFF(rowA, cp);
    int offL1 = SWOFF(rowA, cp+1);
    const __nv_bfloat16* gA = g_Fb + (size_t)(row0+rowA)*Dn + cp*8;

    uint32_t asb = (uint32_t)__cvta_generic_to_shared(&As[0][0]);
    uint32_t bsb = (uint32_t)__cvta_generic_to_shared(&Bs[0][0]);

    // ldmatrix per-lane offsets
    int q = lane>>3, rr = lane&7;
    int offA_ld[2][2], offB_ld[4][2];
    #pragma unroll
    for (int mt=0; mt<2; mt++)
        #pragma unroll
        for (int ks=0; ks<2; ks++){
            int row = wm*32 + mt*16 + rr + (q&1)*8;
            int ch  = ks*2 + (q>>1);
            offA_ld[mt][ks] = SWOFF(row, ch);
        }
    #pragma unroll
    for (int nt4=0; nt4<4; nt4++)
        #pragma unroll
        for (int ks=0; ks<2; ks++){
            int row = wn*64 + nt4*16 + rr + (q>>1)*8;
            int ch  = ks*2 + (q&1);
            offB_ld[nt4][ks] = SWOFF(row, ch);
        }

    // per-thread anchor rows: x = mt*2 + h, row = row0 + wm*32 + mt*16 + h*8 + lane/4
    int   r4[4], labi[4], cami[4];
    float sqi[4], ar[4], tsi[4];
    #pragma unroll
    for (int x=0;x<4;x++){
        int ri = row0 + wm*32 + (x>>1)*16 + (x&1)*8 + (lane>>2);
        r4[x]=ri; sqi[x]=g_sq[ri]; ar[x]=g_invn[ri]*(IT*L2E);
        tsi[x]=ts[ri]; labi[x]=lab[ri]; cami[x]=cam[ri]*NCAMS;
    }
    float sume4[4], spos4[4], cpos4[4], hp4[4], hn4[4];
    #pragma unroll
    for (int x=0;x<4;x++){ sume4[x]=0.f; spos4[x]=0.f; cpos4[x]=0.f; hp4[x]=-BIGF; hn4[x]=BIGF; }

    for (int ct=0; ct<CT_PER; ct++){
        int col0 = blockIdx.y*COLS_PER + ct*BN2;
        const __nv_bfloat16* gB = g_Fb + (size_t)(col0+rowA)*Dn + cp*8;

        if (tid < BN2){
            int cj = col0 + tid;
            s_sq[tid]=g_sq[cj]; s_invn[tid]=g_invn[cj]; s_ts[tid]=ts[cj];
            s_lab[tid]=lab[cj]; s_cam[tid]=cam[cj];
        }
        { // preload buffer 0
            uint4 va0 = *(const uint4*)(gA);
            uint4 va1 = *(const uint4*)(gA+8);
            uint4 vb0 = *(const uint4*)(gB);
            uint4 vb1 = *(const uint4*)(gB+8);
            *(uint4*)(As[0]+offL0)=va0; *(uint4*)(As[0]+offL1)=va1;
            *(uint4*)(Bs[0]+offL0)=vb0; *(uint4*)(Bs[0]+offL1)=vb1;
        }
        __syncthreads();

        float acc[2][8][4];
        #pragma unroll
        for (int i=0;i<2;i++)
            #pragma unroll
            for (int j=0;j<8;j++)
                #pragma unroll
                for (int e=0;e<4;e++) acc[i][j][e]=0.f;

        int buf = 0;
        for (int kt=0; kt<KT2; kt++){
            uint4 va0,va1,vb0,vb1;
            bool pf = (kt+1 < KT2);
            if (pf){
                const __nv_bfloat16* pa = gA + (kt+1)*BKb;
                const __nv_bfloat16* pb = gB + (kt+1)*BKb;
                va0=*(const uint4*)(pa); va1=*(const uint4*)(pa+8);
                vb0=*(const uint4*)(pb); vb1=*(const uint4*)(pb+8);
            }
            uint32_t ab = asb + buf*8192, bbx = bsb + buf*8192;
            #pragma unroll
            for (int ks=0; ks<2; ks++){
                uint32_t a[2][4], b[8][2];
                ldm4(a[0][0],a[0][1],a[0][2],a[0][3], ab + offA_ld[0][ks]);
                ldm4(a[1][0],a[1][1],a[1][2],a[1][3], ab + offA_ld[1][ks]);
                #pragma unroll
                for (int nt4=0; nt4<4; nt4++)
                    ldm4(b[nt4*2][0],b[nt4*2][1],b[nt4*2+1][0],b[nt4*2+1][1], bbx + offB_ld[nt4][ks]);
                #pragma unroll
                for (int mt=0; mt<2; mt++)
                    #pragma unroll
                    for (int nt=0; nt<8; nt++)
                        mma16816(acc[mt][nt], a[mt], b[nt]);
            }
            if (pf){
                char* da = As[buf^1]; char* db = Bs[buf^1];
                *(uint4*)(da+offL0)=va0; *(uint4*)(da+offL1)=va1;
                *(uint4*)(db+offL0)=vb0; *(uint4*)(db+offL1)=vb1;
                __syncthreads();
                buf ^= 1;
            }
        }

        // fused epilogue
        #pragma unroll
        for (int mt=0; mt<2; mt++)
            #pragma unroll
            for (int nt=0; nt<8; nt++)
                #pragma unroll
                for (int e=0; e<4; e++){
                    int x  = mt*2 + (e>>1);
                    int cl = wn*64 + nt*8 + (lane&3)*2 + (e&1);
                    int cj = col0 + cl;
                    float g  = acc[mt][nt][e];
                    float d2 = fmaxf(fmaf(-2.f, g, sqi[x]+s_sq[cl]), 0.f);
                    bool eye  = (r4[x] == cj);
                    bool same = (labi[x] == s_lab[cl]);
                    if (same && !eye) hp4[x] = fmaxf(hp4[x], d2);
                    else              hn4[x] = fminf(hn4[x], d2);
                    float tt = fmaf(g*ar[x], s_invn[cl], -CEXP);   // sim*log2e - IT*log2e
                    float ev; asm("ex2.approx.ftz.f32 %0, %1;" : "=f"(ev) : "f"(tt));
                    sume4[x] += ev;
                    float dt = fabsf(tsi[x] - s_ts[cl]);
                    bool stp = same && !eye && (dt <= s_reach[cami[x] + s_cam[cl]]);
                    if (stp){ spos4[x] += fmaf(tt, LN2f, IT); cpos4[x] += 1.f; }
                }
        __syncthreads();
    }

    // reduce across the 4 lanes sharing each row (lane&3 group), then merge
    #pragma unroll
    for (int o=1;o<=2;o<<=1){
        #pragma unroll
        for (int x=0;x<4;x++){
            sume4[x] += __shfl_xor_sync(0xffffffffu, sume4[x], o);
            spos4[x] += __shfl_xor_sync(0xffffffffu, spos4[x], o);
            cpos4[x] += __shfl_xor_sync(0xffffffffu, cpos4[x], o);
            hp4[x] = fmaxf(hp4[x], __shfl_xor_sync(0xffffffffu, hp4[x], o));
            hn4[x] = fminf(hn4[x], __shfl_xor_sync(0xffffffffu, hn4[x], o));
        }
    }
    if ((lane&3)==0){
        #pragma unroll
        for (int x=0;x<4;x++){
            int ri = r4[x];
            atomicAdd(&g_sume[ri], sume4[x]);
            atomicAdd(&g_spos[ri], spos4[x]);
            atomicAdd(&g_cpos[ri], cpos4[x]);
            atomicMax(&g_hp[ri], f2o(hp4[x]));
            atomicMin(&g_hn[ri], f2o(hn4[x]));
        }
    }
}

// ---------------- classifier (tensor cores) ----------------
__global__ __launch_bounds__(256) void cls_kernel(
    const float* __restrict__ bbias, const int* __restrict__ lab)
{
    __shared__ alignas(16) char As[2][8192];
    __shared__ alignas(16) char Bs[2][8192];
    __shared__ float s_b[BN2];

    int tid = threadIdx.x, lane = tid&31, wid = tid>>5;
    int row0 = blockIdx.x*BM;
    int col0 = blockIdx.y*BN2;
    int wm = wid&3, wn = wid>>2;

    int rowA = tid>>1;
    int cp   = (tid&1)*2;
    int offL0 = SWOFF(rowA, cp);
    int offL1 = SWOFF(rowA, cp+1);
    const __nv_bfloat16* gA = g_Fb + (size_t)(row0+rowA)*Dn + cp*8;
    const __nv_bfloat16* gB = g_Wb + (size_t)(col0+rowA)*Dn + cp*8;

    uint32_t asb = (uint32_t)__cvta_generic_to_shared(&As[0][0]);
    uint32_t bsb = (uint32_t)__cvta_generic_to_shared(&Bs[0][0]);

    int q = lane>>3, rr = lane&7;
    int offA_ld[2][2], offB_ld[4][2];
    #pragma unroll
    for (int mt=0; mt<2; mt++)
        #pragma unroll
        for (int ks=0; ks<2; ks++){
            int row = wm*32 + mt*16 + rr + (q&1)*8;
            int ch  = ks*2 + (q>>1);
            offA_ld[mt][ks] = SWOFF(row, ch);
        }
    #pragma unroll
    for (int nt4=0; nt4<4; nt4++)
        #pragma unroll
        for (int ks=0; ks<2; ks++){
            int row = wn*64 + nt4*16 + rr + (q>>1)*8;
            int ch  = ks*2 + (q&1);
            offB_ld[nt4][ks] = SWOFF(row, ch);
        }

    if (tid < BN2){
        int cj = col0 + tid;
        s_b[tid] = (cj < Cn) ? bbias[cj] : 0.f;
    }
    { // preload buffer 0
        uint4 va0 = *(const uint4*)(gA);
        uint4 va1 = *(const uint4*)(gA+8);
        uint4 vb0 = *(const uint4*)(gB);
        uint4 vb1 = *(const uint4*)(gB+8);
        *(uint4*)(As[0]+offL0)=va0; *(uint4*)(As[0]+offL1)=va1;
        *(uint4*)(Bs[0]+offL0)=vb0; *(uint4*)(Bs[0]+offL1)=vb1;
    }
    __syncthreads();

    float acc[2][8][4];
    #pragma unroll
    for (int i=0;i<2;i++)
        #pragma unroll
        for (int j=0;j<8;j++)
            #pragma unroll
            for (int e=0;e<4;e++) acc[i][j][e]=0.f;

    int buf = 0;
    for (int kt=0; kt<KT2; kt++){
        uint4 va0,va1,vb0,vb1;
        bool pf = (kt+1 < KT2);
        if (pf){
            const __nv_bfloat16* pa = gA + (kt+1)*BKb;
            const __nv_bfloat16* pb = gB + (kt+1)*BKb;
            va0=*(const uint4*)(pa); va1=*(const uint4*)(pa+8);
            vb0=*(const uint4*)(pb); vb1=*(const uint4*)(pb+8);
        }
        uint32_t ab = asb + buf*8192, bbx = bsb + buf*8192;
        #pragma unroll
        for (int ks=0; ks<2; ks++){
            uint32_t a[2][4], b[8][2];
            ldm4(a[0][0],a[0][1],a[0][2],a[0][3], ab + offA_ld[0][ks]);
            ldm4(a[1][0],a[1][1],a[1][2],a[1][3], ab + offA_ld[1][ks]);
            #pragma unroll
            for (int nt4=0; nt4<4; nt4++)
                ldm4(b[nt4*2][0],b[nt4*2][1],b[nt4*2+1][0],b[nt4*2+1][1], bbx + offB_ld[nt4][ks]);
            #pragma unroll
            for (int mt=0; mt<2; mt++)
                #pragma unroll
                for (int nt=0; nt<8; nt++)
                    mma16816(acc[mt][nt], a[mt], b[nt]);
        }
        if (pf){
            char* da = As[buf^1]; char* db = Bs[buf^1];
            *(uint4*)(da+offL0)=va0; *(uint4*)(da+offL1)=va1;
            *(uint4*)(db+offL0)=vb0; *(uint4*)(db+offL1)=vb1;
            __syncthreads();
            buf ^= 1;
        }
    }

    int r4[4], labi[4];
    float se4[4];
    #pragma unroll
    for (int x=0;x<4;x++){
        int ri = row0 + wm*32 + (x>>1)*16 + (x&1)*8 + (lane>>2);
        r4[x]=ri; labi[x]=lab[ri]; se4[x]=0.f;
    }
    #pragma unroll
    for (int mt=0; mt<2; mt++)
        #pragma unroll
        for (int nt=0; nt<8; nt++)
            #pragma unroll
            for (int e=0; e<4; e++){
                int x  = mt*2 + (e>>1);
                int cl = wn*64 + nt*8 + (lane&3)*2 + (e&1);
                int cj = col0 + cl;
                float logit = acc[mt][nt][e] + s_b[cl];
                if (cj < Cn){
                    se4[x] += __expf(logit);
                    if (cj == labi[x]) g_lab_logit[r4[x]] = logit;
                }
            }
    #pragma unroll
    for (int o=1;o<=2;o<<=1)
        #pragma unroll
        for (int x=0;x<4;x++)
            se4[x] += __shfl_xor_sync(0xffffffffu, se4[x], o);
    if ((lane&3)==0){
        #pragma unroll
        for (int x=0;x<4;x++) atomicAdd(&g_sume_cls[r4[x]], se4[x]);
    }
}

// ---------------- final reductions ----------------
__global__ void fin1(){
    int i = blockIdx.x*blockDim.x + threadIdx.x;
    float tri=0.f, nv=0.f, stn=0.f, stc=0.f, cls=0.f;
    if (i < Bn){
        float lse = IT + logf(g_sume[i]);
        stn = g_spos[i] - g_cpos[i]*lse;
        stc = g_cpos[i];
        float hp = o2f(g_hp[i]), hn = o2f(g_hn[i]);
        bool valid = hp > -1.0e8f;
        tri = valid ? fmaxf(hp - hn + MARGINF, 0.f) : 0.f;
        nv  = valid ? 1.f : 0.f;
        cls = logf(g_sume_cls[i]) - g_lab_logit[i];
    }
    #pragma unroll
    for (int o=16;o;o>>=1){
        tri += __shfl_down_sync(0xffffffffu, tri, o);
        nv  += __shfl_down_sync(0xffffffffu, nv , o);
        stn += __shfl_down_sync(0xffffffffu, stn, o);
        stc += __shfl_down_sync(0xffffffffu, stc, o);
        cls += __shfl_down_sync(0xffffffffu, cls, o);
    }
    if ((threadIdx.x & 31) == 0){
        atomicAdd(&g_acc[0], tri);
        atomicAdd(&g_acc[1], nv);
        atomicAdd(&g_acc[2], stn);
        atomicAdd(&g_acc[3], stc);
        atomicAdd(&g_acc[4], cls);
    }
}

__global__ void fin2(float* out){
    float nv = g_acc[1], npos = g_acc[3];
    float loss_id  = g_acc[4] / (float)Bn;
    float loss_tri = (nv   > 0.f) ? g_acc[0] / fmaxf(nv,   1.f) : 0.f;
    float loss_st  = (npos > 0.f) ? (-g_acc[2]) / fmaxf(npos, 1.f) : 0.f;
    out[0] = loss_id + L_TRI*loss_tri + L_ST*loss_st;
}

// ---------------- launch ----------------
extern "C" void kernel_launch(void* const* d_in, const int* in_sizes, int n_in,
                              void* d_out, int out_size){
    const float* F     = (const float*)d_in[0];
    const int*   lab   = (const int*)  d_in[1];
    const int*   cam   = (const int*)  d_in[2];
    const float* ts    = (const float*)d_in[3];
    const float* reach = (const float*)d_in[4];
    const float* W     = (const float*)d_in[5];
    const float* bbias = (const float*)d_in[6];
    float* out = (float*)d_out;

    convert_F_kernel<<<(Bn*(size_t)Dn/8)/256, 256>>>(F);
    convert_W_kernel<<<((size_t)CnP*Dn/8)/256, 256>>>(W);
    init_kernel<<<(Bn+255)/256, 256>>>();
    norm_kernel<<<Bn/8, 256>>>();
    dim3 g1(Bn/BM, NSPLIT);
    pair_kernel<<<g1, 256>>>(lab, cam, ts, reach);
    dim3 g2(Bn/BM, CnP/BN2);
    cls_kernel<<<g2, 256>>>(bbias, lab);
    fin1<<<Bn/256, 256>>>();
    fin2<<<1,1>>>(out);
}

// round 4
// speedup vs baseline: 5.3806x; 1.1270x over previous
#include <cuda_runtime.h>
#include <cuda_bf16.h>
#include <cstdint>

#define Bn 8192
#define Dn 2048
#define Cn 751
#define CnP 768
#define NCAMS 16
#define MARGINF 0.3f
#define IT (1.0f/0.07f)
#define L2E 1.44269504f
#define LN2f 0.69314718f
#define CEXP (IT*L2E)
#define BIGF 1.0e9f
#define L_TRI 0.5f
#define L_ST 0.3f

// tiling
#define BM 128
#define BN 256
#define BKp 32
#define KTp (Dn/BKp)            // 64
#define CTp 4                   // column tiles per CTA
#define COLS_PER (BN*CTp)       // 1024
#define NSPLIT (Bn/COLS_PER)    // 8
#define JMAXp (CTp*KTp)         // 256
#define STG 24576               // stage bytes: A 8KB + B 16KB
#define SM_REACH (4*STG)        // 98304
#define SM_SQ  (SM_REACH+1024)
#define SM_INV (SM_SQ+1024)
#define SM_TS  (SM_INV+1024)
#define SM_LAB (SM_TS+1024)
#define SM_CAM (SM_LAB+1024)
#define SMEM_PAIR (SM_CAM+1024) // 104448
#define SMEM_CLS (4*STG+1024)   // 99328

// swizzled smem offset within a 64B-row tile
#define SW(row, ch) ((row)*64 + ((((ch) ^ (((row)>>1)&3)))<<4))

// ---------------- device scratch ----------------
__device__ __nv_bfloat16 g_Fb[(size_t)Bn*Dn];
__device__ __nv_bfloat16 g_Wb[(size_t)CnP*Dn];
__device__ float    g_sq[Bn], g_invn[Bn];
__device__ float    g_sume[Bn], g_spos[Bn], g_cpos[Bn];
__device__ unsigned g_hp[Bn], g_hn[Bn];
__device__ float    g_sume_cls[Bn], g_lab_logit[Bn];
__device__ float    g_acc[8];

__device__ __forceinline__ unsigned f2o(float f){
    unsigned u = __float_as_uint(f);
    return (u & 0x80000000u) ? ~u : (u | 0x80000000u);
}
__device__ __forceinline__ float o2f(unsigned u){
    return __uint_as_float((u & 0x80000000u) ? (u & 0x7fffffffu) : ~u);
}
__device__ __forceinline__ uint32_t pack_bf(float a, float b){
    __nv_bfloat162 t = __floats2bfloat162_rn(a, b);
    return *reinterpret_cast<uint32_t*>(&t);
}
__device__ __forceinline__ float sq2(uint32_t u){
    __nv_bfloat162 h = *reinterpret_cast<__nv_bfloat162*>(&u);
    float2 f = __bfloat1622float2(h);
    return f.x*f.x + f.y*f.y;
}

#define CP16(dst, src) asm volatile("cp.async.cg.shared.global [%0], [%1], 16;" :: "r"(dst), "l"(src) : "memory")
#define CP_COMMIT()    asm volatile("cp.async.commit_group;" ::: "memory")
#define CP_WAIT(n)     asm volatile("cp.async.wait_group %0;" :: "n"(n) : "memory")

__device__ __forceinline__ void ldm4(uint32_t &r0, uint32_t &r1, uint32_t &r2, uint32_t &r3, uint32_t addr){
    asm volatile("ldmatrix.sync.aligned.m8n8.x4.shared.b16 {%0,%1,%2,%3}, [%4];"
        : "=r"(r0), "=r"(r1), "=r"(r2), "=r"(r3) : "r"(addr));
}
__device__ __forceinline__ void mma16816(float* d, const uint32_t* a, const uint32_t* b){
    asm volatile("mma.sync.aligned.m16n8k16.row.col.f32.bf16.bf16.f32 "
        "{%0,%1,%2,%3}, {%4,%5,%6,%7}, {%8,%9}, {%0,%1,%2,%3};"
        : "+f"(d[0]), "+f"(d[1]), "+f"(d[2]), "+f"(d[3])
        : "r"(a[0]), "r"(a[1]), "r"(a[2]), "r"(a[3]), "r"(b[0]), "r"(b[1]));
}

// ---------------- conversion / init / norms ----------------
__global__ void convert_F_kernel(const float* __restrict__ F){
    size_t i = ((size_t)blockIdx.x*blockDim.x + threadIdx.x)*8;
    float4 v0 = *(const float4*)(F+i);
    float4 v1 = *(const float4*)(F+i+4);
    uint4 o;
    o.x = pack_bf(v0.x, v0.y); o.y = pack_bf(v0.z, v0.w);
    o.z = pack_bf(v1.x, v1.y); o.w = pack_bf(v1.z, v1.w);
    *(uint4*)(g_Fb + i) = o;
}
__global__ void convert_W_kernel(const float* __restrict__ W){
    size_t i = ((size_t)blockIdx.x*blockDim.x + threadIdx.x)*8;
    size_t row = i / Dn;
    uint4 o;
    if (row < Cn){
        float4 v0 = *(const float4*)(W+i);
        float4 v1 = *(const float4*)(W+i+4);
        o.x = pack_bf(v0.x, v0.y); o.y = pack_bf(v0.z, v0.w);
        o.z = pack_bf(v1.x, v1.y); o.w = pack_bf(v1.z, v1.w);
    } else { o.x=o.y=o.z=o.w=0u; }
    *(uint4*)(g_Wb + i) = o;
}
__global__ void init_kernel(){
    int i = blockIdx.x*blockDim.x + threadIdx.x;
    if (i < Bn){
        g_sume[i]=0.f; g_spos[i]=0.f; g_cpos[i]=0.f;
        g_hp[i]=f2o(-BIGF); g_hn[i]=f2o(BIGF);
        g_sume_cls[i]=0.f; g_lab_logit[i]=0.f;
    }
    if (i < 8) g_acc[i]=0.f;
}
__global__ void norm_kernel(){
    int row  = blockIdx.x*(blockDim.x>>5) + (threadIdx.x>>5);
    int lane = threadIdx.x & 31;
    const uint4* p = (const uint4*)(g_Fb + (size_t)row*Dn);
    float s = 0.f;
    #pragma unroll
    for (int i = lane; i < Dn/8; i += 32){
        uint4 v = p[i];
        s += sq2(v.x) + sq2(v.y) + sq2(v.z) + sq2(v.w);
    }
    #pragma unroll
    for (int o=16;o;o>>=1) s += __shfl_xor_sync(0xffffffffu, s, o);
    if (lane==0){ g_sq[row]=s; g_invn[row]=rsqrtf(s); }
}

// ---------------- fused Gram kernel (mma.sync, cp.async 4-stage) ----------------
__global__ __launch_bounds__(512) void pair_kernel(
    const int* __restrict__ lab, const int* __restrict__ cam,
    const float* __restrict__ ts, const float* __restrict__ reach)
{
    extern __shared__ char smem[];
    uint32_t sb = (uint32_t)__cvta_generic_to_shared(smem);
    int tid = threadIdx.x, lane = tid&31, wid = tid>>5;
    int wm = wid&3, wn = wid>>2;
    int row0 = blockIdx.x*BM;
    int colstart = blockIdx.y*COLS_PER;

    float* s_reach=(float*)(smem+SM_REACH);
    float* s_sq  =(float*)(smem+SM_SQ);
    float* s_invn=(float*)(smem+SM_INV);
    float* s_ts  =(float*)(smem+SM_TS);
    int*   s_lab =(int*)  (smem+SM_LAB);
    int*   s_cam =(int*)  (smem+SM_CAM);
    if (tid < 256) s_reach[tid] = reach[tid];

    // loader mapping: A = 512 chunks (1/thread), B = 1024 chunks (2/thread)
    int rA = tid>>2, cA = tid&3;
    uint32_t dA = SW(rA, cA);
    const __nv_bfloat16* gA = g_Fb + (size_t)(row0+rA)*Dn + cA*8;
    int rB1 = (tid+512)>>2;
    uint32_t dB0 = 8192 + SW(rA, cA);
    uint32_t dB1 = 8192 + SW(rB1, cA);
    const __nv_bfloat16* gB0 = g_Fb + (size_t)(colstart+rA)*Dn + cA*8;
    const __nv_bfloat16* gB1 = g_Fb + (size_t)(colstart+rB1)*Dn + cA*8;

    // ldmatrix per-lane offsets
    int q = lane>>3, rr = lane&7;
    int offA_ld[2][2], offB_ld[4][2];
    #pragma unroll
    for (int mt=0; mt<2; mt++)
        #pragma unroll
        for (int ks=0; ks<2; ks++){
            int row = wm*32 + mt*16 + rr + (q&1)*8;
            offA_ld[mt][ks] = SW(row, ks*2 + (q>>1));
        }
    #pragma unroll
    for (int nt4=0; nt4<4; nt4++)
        #pragma unroll
        for (int ks=0; ks<2; ks++){
            int row = wn*64 + nt4*16 + rr + (q>>1)*8;
            offB_ld[nt4][ks] = 8192 + SW(row, ks*2 + (q&1));
        }

    float acc[2][8][4];
    #pragma unroll
    for (int i=0;i<2;i++)
        #pragma unroll
        for (int j=0;j<8;j++)
            #pragma unroll
            for (int e=0;e<4;e++) acc[i][j][e]=0.f;
    float sume4[4], spos4[4], cpos4[4], hp4[4], hn4[4];
    #pragma unroll
    for (int x=0;x<4;x++){ sume4[x]=0.f; spos4[x]=0.f; cpos4[x]=0.f; hp4[x]=-BIGF; hn4[x]=BIGF; }

    #define PLOAD(j) do { \
        int _ct=(j)>>6, _kt=(j)&63; \
        uint32_t _st = sb + ((j)&3)*STG; \
        size_t _ko = (size_t)_kt*BKp; \
        size_t _co = (size_t)_ct*((size_t)BN*Dn); \
        CP16(_st+dA,  gA  + _ko); \
        CP16(_st+dB0, gB0 + _co + _ko); \
        CP16(_st+dB1, gB1 + _co + _ko); \
    } while(0)

    PLOAD(0); CP_COMMIT();
    PLOAD(1); CP_COMMIT();
    PLOAD(2); CP_COMMIT();

    for (int j=0; j<JMAXp; j++){
        CP_WAIT(2);
        __syncthreads();
        if ((j&63)==0 && tid<256){          // column metadata for this ct
            int cj = colstart + (j>>6)*BN + tid;
            s_sq[tid]=g_sq[cj]; s_invn[tid]=g_invn[cj]; s_ts[tid]=ts[cj];
            s_lab[tid]=lab[cj]; s_cam[tid]=cam[cj];
        }
        if (j+3 < JMAXp) PLOAD(j+3);
        CP_COMMIT();

        uint32_t st = sb + (j&3)*STG;
        #pragma unroll
        for (int ks=0; ks<2; ks++){
            uint32_t a[2][4], b[8][2];
            ldm4(a[0][0],a[0][1],a[0][2],a[0][3], st + offA_ld[0][ks]);
            ldm4(a[1][0],a[1][1],a[1][2],a[1][3], st + offA_ld[1][ks]);
            #pragma unroll
            for (int nt4=0; nt4<4; nt4++)
                ldm4(b[nt4*2][0],b[nt4*2][1],b[nt4*2+1][0],b[nt4*2+1][1], st + offB_ld[nt4][ks]);
            #pragma unroll
            for (int mt=0; mt<2; mt++)
                #pragma unroll
                for (int nt=0; nt<8; nt++)
                    mma16816(acc[mt][nt], a[mt], b[nt]);
        }

        if ((j&63)==63){
            int col0 = colstart + (j>>6)*BN;
            #pragma unroll
            for (int mt=0; mt<2; mt++)
                #pragma unroll
                for (int h=0; h<2; h++){
                    int x = mt*2 + h;
                    int ri = row0 + wm*32 + mt*16 + h*8 + (lane>>2);
                    float sqi = g_sq[ri], ari = g_invn[ri]*CEXP, tsi = ts[ri];
                    int labi = lab[ri], cami = cam[ri]*NCAMS;
                    #pragma unroll
                    for (int nt=0; nt<8; nt++){
                        int cl = wn*64 + nt*8 + (lane&3)*2;
                        #pragma unroll
                        for (int u=0; u<2; u++){
                            int clu = cl+u, cj = col0+clu;
                            float g  = acc[mt][nt][h*2+u];
                            float d2 = fmaxf(fmaf(-2.f, g, sqi + s_sq[clu]), 0.f);
                            bool eye  = (ri == cj);
                            bool same = (labi == s_lab[clu]);
                            if (same && !eye) hp4[x] = fmaxf(hp4[x], d2);
                            else              hn4[x] = fminf(hn4[x], d2);
                            float tt = fmaf(g*ari, s_invn[clu], -CEXP);
                            float ev; asm("ex2.approx.ftz.f32 %0, %1;" : "=f"(ev) : "f"(tt));
                            sume4[x] += ev;
                            float dt = fabsf(tsi - s_ts[clu]);
                            if (same && !eye && dt <= s_reach[cami + s_cam[clu]]){
                                spos4[x] += fmaf(tt, LN2f, IT); cpos4[x] += 1.f;
                            }
                        }
                    }
                }
            #pragma unroll
            for (int i=0;i<2;i++)
                #pragma unroll
                for (int t=0;t<8;t++)
                    #pragma unroll
                    for (int e=0;e<4;e++) acc[i][t][e]=0.f;
        }
    }

    // reduce across the 4 lanes sharing each row, then merge globally
    #pragma unroll
    for (int o=1;o<=2;o<<=1){
        #pragma unroll
        for (int x=0;x<4;x++){
            sume4[x] += __shfl_xor_sync(0xffffffffu, sume4[x], o);
            spos4[x] += __shfl_xor_sync(0xffffffffu, spos4[x], o);
            cpos4[x] += __shfl_xor_sync(0xffffffffu, cpos4[x], o);
            hp4[x] = fmaxf(hp4[x], __shfl_xor_sync(0xffffffffu, hp4[x], o));
            hn4[x] = fminf(hn4[x], __shfl_xor_sync(0xffffffffu, hn4[x], o));
        }
    }
    if ((lane&3)==0){
        #pragma unroll
        for (int x=0;x<4;x++){
            int ri = row0 + wm*32 + (x>>1)*16 + (x&1)*8 + (lane>>2);
            atomicAdd(&g_sume[ri], sume4[x]);
            atomicAdd(&g_spos[ri], spos4[x]);
            atomicAdd(&g_cpos[ri], cpos4[x]);
            atomicMax(&g_hp[ri], f2o(hp4[x]));
            atomicMin(&g_hn[ri], f2o(hn4[x]));
        }
    }
    #undef PLOAD
}

// ---------------- classifier (mma.sync, cp.async 4-stage) ----------------
__global__ __launch_bounds__(512) void cls_kernel(
    const float* __restrict__ bbias, const int* __restrict__ lab)
{
    extern __shared__ char smem[];
    uint32_t sb = (uint32_t)__cvta_generic_to_shared(smem);
    int tid = threadIdx.x, lane = tid&31, wid = tid>>5;
    int wm = wid&3, wn = wid>>2;
    int row0 = blockIdx.x*BM;
    int col0 = blockIdx.y*BN;
    float* s_b = (float*)(smem + 4*STG);
    if (tid < 256){
        int cj = col0 + tid;
        s_b[tid] = (cj < Cn) ? bbias[cj] : 0.f;
    }

    int rA = tid>>2, cA = tid&3;
    uint32_t dA = SW(rA, cA);
    const __nv_bfloat16* gA = g_Fb + (size_t)(row0+rA)*Dn + cA*8;
    int rB1 = (tid+512)>>2;
    uint32_t dB0 = 8192 + SW(rA, cA);
    uint32_t dB1 = 8192 + SW(rB1, cA);
    const __nv_bfloat16* gB0 = g_Wb + (size_t)(col0+rA)*Dn + cA*8;
    const __nv_bfloat16* gB1 = g_Wb + (size_t)(col0+rB1)*Dn + cA*8;

    int q = lane>>3, rr = lane&7;
    int offA_ld[2][2], offB_ld[4][2];
    #pragma unroll
    for (int mt=0; mt<2; mt++)
        #pragma unroll
        for (int ks=0; ks<2; ks++){
            int row = wm*32 + mt*16 + rr + (q&1)*8;
            offA_ld[mt][ks] = SW(row, ks*2 + (q>>1));
        }
    #pragma unroll
    for (int nt4=0; nt4<4; nt4++)
        #pragma unroll
        for (int ks=0; ks<2; ks++){
            int row = wn*64 + nt4*16 + rr + (q>>1)*8;
            offB_ld[nt4][ks] = 8192 + SW(row, ks*2 + (q&1));
        }

    float acc[2][8][4];
    #pragma unroll
    for (int i=0;i<2;i++)
        #pragma unroll
        for (int j=0;j<8;j++)
            #pragma unroll
            for (int e=0;e<4;e++) acc[i][j][e]=0.f;

    #define CLOAD(j) do { \
        uint32_t _st = sb + ((j)&3)*STG; \
        size_t _ko = (size_t)(j)*BKp; \
        CP16(_st+dA,  gA  + _ko); \
        CP16(_st+dB0, gB0 + _ko); \
        CP16(_st+dB1, gB1 + _ko); \
    } while(0)

    CLOAD(0); CP_COMMIT();
    CLOAD(1); CP_COMMIT();
    CLOAD(2); CP_COMMIT();

    for (int j=0; j<KTp; j++){
        CP_WAIT(2);
        __syncthreads();
        if (j+3 < KTp) CLOAD(j+3);
        CP_COMMIT();
        uint32_t st = sb + (j&3)*STG;
        #pragma unroll
        for (int ks=0; ks<2; ks++){
            uint32_t a[2][4], b[8][2];
            ldm4(a[0][0],a[0][1],a[0][2],a[0][3], st + offA_ld[0][ks]);
            ldm4(a[1][0],a[1][1],a[1][2],a[1][3], st + offA_ld[1][ks]);
            #pragma unroll
            for (int nt4=0; nt4<4; nt4++)
                ldm4(b[nt4*2][0],b[nt4*2][1],b[nt4*2+1][0],b[nt4*2+1][1], st + offB_ld[nt4][ks]);
            #pragma unroll
            for (int mt=0; mt<2; mt++)
                #pragma unroll
                for (int nt=0; nt<8; nt++)
                    mma16816(acc[mt][nt], a[mt], b[nt]);
        }
    }

    float se4[4];
    #pragma unroll
    for (int x=0;x<4;x++) se4[x]=0.f;
    #pragma unroll
    for (int mt=0; mt<2; mt++)
        #pragma unroll
        for (int h=0; h<2; h++){
            int x = mt*2 + h;
            int ri = row0 + wm*32 + mt*16 + h*8 + (lane>>2);
            int labi = lab[ri];
            #pragma unroll
            for (int nt=0; nt<8; nt++){
                int cl = wn*64 + nt*8 + (lane&3)*2;
                #pragma unroll
                for (int u=0; u<2; u++){
                    int clu = cl+u, cj = col0+clu;
                    float logit = acc[mt][nt][h*2+u] + s_b[clu];
                    if (cj < Cn){
                        se4[x] += __expf(logit);
                        if (cj == labi) g_lab_logit[ri] = logit;
                    }
                }
            }
        }
    #pragma unroll
    for (int o=1;o<=2;o<<=1)
        #pragma unroll
        for (int x=0;x<4;x++)
            se4[x] += __shfl_xor_sync(0xffffffffu, se4[x], o);
    if ((lane&3)==0){
        #pragma unroll
        for (int x=0;x<4;x++){
            int ri = row0 + wm*32 + (x>>1)*16 + (x&1)*8 + (lane>>2);
            atomicAdd(&g_sume_cls[ri], se4[x]);
        }
    }
    #undef CLOAD
}

// ---------------- final reductions ----------------
__global__ void fin1(){
    int i = blockIdx.x*blockDim.x + threadIdx.x;
    float tri=0.f, nv=0.f, stn=0.f, stc=0.f, cls=0.f;
    if (i < Bn){
        float lse = IT + logf(g_sume[i]);
        stn = g_spos[i] - g_cpos[i]*lse;
        stc = g_cpos[i];
        float hp = o2f(g_hp[i]), hn = o2f(g_hn[i]);
        bool valid = hp > -1.0e8f;
        tri = valid ? fmaxf(hp - hn + MARGINF, 0.f) : 0.f;
        nv  = valid ? 1.f : 0.f;
        cls = logf(g_sume_cls[i]) - g_lab_logit[i];
    }
    #pragma unroll
    for (int o=16;o;o>>=1){
        tri += __shfl_down_sync(0xffffffffu, tri, o);
        nv  += __shfl_down_sync(0xffffffffu, nv , o);
        stn += __shfl_down_sync(0xffffffffu, stn, o);
        stc += __shfl_down_sync(0xffffffffu, stc, o);
        cls += __shfl_down_sync(0xffffffffu, cls, o);
    }
    if ((threadIdx.x & 31) == 0){
        atomicAdd(&g_acc[0], tri);
        atomicAdd(&g_acc[1], nv);
        atomicAdd(&g_acc[2], stn);
        atomicAdd(&g_acc[3], stc);
        atomicAdd(&g_acc[4], cls);
    }
}
__global__ void fin2(float* out){
    float nv = g_acc[1], npos = g_acc[3];
    float loss_id  = g_acc[4] / (float)Bn;
    float loss_tri = (nv   > 0.f) ? g_acc[0] / fmaxf(nv,   1.f) : 0.f;
    float loss_st  = (npos > 0.f) ? (-g_acc[2]) / fmaxf(npos, 1.f) : 0.f;
    out[0] = loss_id + L_TRI*loss_tri + L_ST*loss_st;
}

// ---------------- launch ----------------
extern "C" void kernel_launch(void* const* d_in, const int* in_sizes, int n_in,
                              void* d_out, int out_size){
    const float* F     = (const float*)d_in[0];
    const int*   lab   = (const int*)  d_in[1];
    const int*   cam   = (const int*)  d_in[2];
    const float* ts    = (const float*)d_in[3];
    const float* reach = (const float*)d_in[4];
    const float* W     = (const float*)d_in[5];
    const float* bbias = (const float*)d_in[6];
    float* out = (float*)d_out;

    static int configured = 0;
    cudaFuncSetAttribute(pair_kernel, cudaFuncAttributeMaxDynamicSharedMemorySize, SMEM_PAIR);
    cudaFuncSetAttribute(cls_kernel,  cudaFuncAttributeMaxDynamicSharedMemorySize, SMEM_CLS);
    (void)configured;

    convert_F_kernel<<<(Bn*(size_t)Dn/8)/256, 256>>>(F);
    convert_W_kernel<<<((size_t)CnP*Dn/8)/256, 256>>>(W);
    init_kernel<<<(Bn+255)/256, 256>>>();
    norm_kernel<<<Bn/8, 256>>>();
    dim3 g1(Bn/BM, NSPLIT);
    pair_kernel<<<g1, 512, SMEM_PAIR>>>(lab, cam, ts, reach);
    dim3 g2(Bn/BM, CnP/BN);
    cls_kernel<<<g2, 512, SMEM_CLS>>>(bbias, lab);
    fin1<<<Bn/256, 256>>>();
    fin2<<<1,1>>>(out);
}